// round 16
// baseline (speedup 1.0000x reference)
#include <cuda_runtime.h>
#include <cstdint>

#define CC   64
#define CINN 66
#define LL   40960
#define WW   256
#define TP   128
#define NTHR 256
#define NINST 32
#define NPARAMS 8513

#define OFF_W0 0
#define OFF_W1 4224
#define OFF_W2 8320
#define OFF_B0 8384
#define OFF_B1 8448
#define OFF_B2 8512
#define MASK_BIAS_SHIFT 2.19f

#define KS 72      // smem word stride per row (288 B) -> conflict-free ldmatrix
#define KP 64      // packed global K (no pad)

// ---- precomputed tf32 operands (device globals; allocation-free) ----
// gX: [img][px][64] tf32 words, plain layout
__device__ __align__(16) uint32_t gX[4 * LL * KP];
// per instance: W0' (64x64 words, coord cols folded out) | W1 (64x64)
#define WIMG_U32 (2 * 64 * KP)
__device__ __align__(16) uint32_t gWt[NINST * WIMG_U32];

// ---- GEMM smem byte offsets ----
#define W0_O 0          // 64 rows * 288
#define W1_O 18432      // 64 rows * 288
#define X_O  36864      // 128 rows * 288
#define H_O  36864      // H aliases X exactly
#define MISC_O 73728
#define SMEM_TOTAL (MISC_O + 2080)   // 75808 B -> 3 blocks/SM

__device__ __forceinline__ uint32_t f2tf(float v) {
    uint32_t r;
    asm("cvt.rna.tf32.f32 %0, %1;" : "=r"(r) : "f"(v));
    return r;
}
__device__ __forceinline__ uint32_t smem_u32(const void* p) {
    uint32_t a;
    asm("{ .reg .u64 t; cvta.to.shared.u64 t, %1; cvt.u32.u64 %0, t; }" : "=r"(a) : "l"(p));
    return a;
}
__device__ __forceinline__ void cpasync16(uint32_t dst, const void* src) {
    asm volatile("cp.async.cg.shared.global [%0], [%1], 16;" :: "r"(dst), "l"(src) : "memory");
}
__device__ __forceinline__ void ldsm4(uint32_t* r, uint32_t addr) {
    asm volatile("ldmatrix.sync.aligned.m8n8.x4.shared.b16 {%0,%1,%2,%3}, [%4];"
                 : "=r"(r[0]), "=r"(r[1]), "=r"(r[2]), "=r"(r[3]) : "r"(addr));
}
__device__ __forceinline__ void ldsm2(uint32_t* r, uint32_t addr) {
    asm volatile("ldmatrix.sync.aligned.m8n8.x2.shared.b16 {%0,%1}, [%2];"
                 : "=r"(r[0]), "=r"(r[1]) : "r"(addr));
}
__device__ __forceinline__ void mmatf32(float* c, const uint32_t* a, uint32_t b0, uint32_t b1) {
    asm volatile(
        "mma.sync.aligned.m16n8k8.row.col.f32.tf32.tf32.f32 "
        "{%0,%1,%2,%3}, {%4,%5,%6,%7}, {%8,%9}, {%0,%1,%2,%3};"
        : "+f"(c[0]), "+f"(c[1]), "+f"(c[2]), "+f"(c[3])
        : "r"(a[0]), "r"(a[1]), "r"(a[2]), "r"(a[3]), "r"(b0), "r"(b1));
}

// ============ fused prep: bx<320 -> X tiles; bx>=320 -> weights ============
__global__ __launch_bounds__(256)
void prep_kernel(const float* __restrict__ x, const float* __restrict__ params)
{
    __shared__ __align__(16) float stage[TP * 89];
    const int bx  = blockIdx.x;
    const int by  = blockIdx.y;       // img (x-prep) / inst sub (w-prep)
    const int tid = threadIdx.x;

    if (bx >= LL / TP) {
        // ---- weight prep: inst = (bx-320)*4 + by ----
        const int inst = (bx - LL / TP) * 4 + by;
        const float* p = params + (size_t)inst * NPARAMS;
        uint32_t* w = gWt + (size_t)inst * WIMG_U32;
        for (int idx = tid; idx < 64 * KP; idx += 256) {
            int m = idx >> 6, k = idx & 63;
            w[idx]             = f2tf(p[OFF_W0 + m * CINN + k + 2]);  // coord cols dropped
            w[64 * KP + idx]   = f2tf(p[OFF_W1 + m * 64 + k]);
        }
        return;
    }

    // ---- X prep ----
    const int img = by;
    const int l0  = bx * TP;
    const float* xb = x + (size_t)img * CC * LL + l0;
    for (int idx = tid; idx < CC * TP; idx += 256) {
        int ch = idx >> 7, px = idx & 127;
        stage[px * 89 + ch] = xb[(size_t)ch * LL + px];
    }
    __syncthreads();

    // vectorized: one uint4 (4 adjacent k) per thread-iter, fully coalesced
    uint4* go = (uint4*)(gX + ((size_t)img * LL + l0) * KP);
    for (int idx = tid; idx < TP * (KP / 4); idx += 256) {
        int px = idx >> 4, c4 = (idx & 15) * 4;
        const float* s = stage + px * 89 + c4;
        uint4 v;
        v.x = f2tf(s[0]); v.y = f2tf(s[1]); v.z = f2tf(s[2]); v.w = f2tf(s[3]);
        go[idx] = v;
    }
}

// ============ main GEMM kernel ============
extern __shared__ __align__(16) char smem[];

__global__ __launch_bounds__(NTHR, 3)
void condlane_mma_kernel(const float* __restrict__ params,
                         float* __restrict__ out)
{
    uint32_t* sw   = (uint32_t*)smem;
    float*    sb0f = (float*)(smem + MISC_O);   // b0 + w0[:,1]*y
    float*    sb1  = sb0f + 64;
    float*    sw2  = sb0f + 128;
    float*    sWx  = sb0f + 192;                // w0[:,0]
    float*    sb2  = sb0f + 256;
    float*    sPart = sb0f + 260;               // [2][128]

    const int bx   = blockIdx.x;
    const int inst = blockIdx.y;
    const int img  = inst >> 3;
    const int tid  = threadIdx.x;
    const int wid  = tid >> 5;
    const int lane = tid & 31;
    const int l0   = bx * TP;
    const uint32_t sb = smem_u32(smem);

    // ---- cp.async copy-in, packed-K global -> strided smem rows ----
    {
        const uint4* wsrc = (const uint4*)(gWt + (size_t)inst * WIMG_U32);
        const uint4* xsrc = (const uint4*)(gX + ((size_t)img * LL + l0) * KP);
        for (int i = tid; i < 2048; i += NTHR) {
            int row = i >> 4, c = i & 15;
            cpasync16(sb + row * 288 + c * 16, wsrc + i);        // W0 rows 0-63, W1 rows 64-127
            cpasync16(sb + X_O + row * 288 + c * 16, xsrc + i);  // X rows 0-127
        }
        const float* p = params + (size_t)inst * NPARAMS;
        const float yc = (float)(l0 >> 8);
        if (tid < 64) {
            sb0f[tid] = p[OFF_B0 + tid] + p[OFF_W0 + tid * CINN + 1] * yc;
            sWx[tid]  = p[OFF_W0 + tid * CINN];
            sb1[tid]  = p[OFF_B1 + tid];
            sw2[tid]  = p[OFF_W2 + tid];
        }
        if (tid == 0) sb2[0] = p[OFF_B2] - MASK_BIAS_SHIFT;
        asm volatile("cp.async.commit_group;\ncp.async.wait_group 0;" ::: "memory");
    }
    __syncthreads();

    // ---- warp tiling: 8 warps = (2 m-halves) x (4 px-groups); 32 rows x 32 px ----
    const int mh = wid & 1;
    const int ng = wid >> 1;
    const int g  = lane >> 2;
    const int t  = lane & 3;

    // ldmatrix per-lane addresses (byte offsets into row-strided tiles)
    // A x4: group(l>>3): {rows+0,k0} {rows+8,k0} {rows+0,k0+4} {rows+8,k0+4}
    const uint32_t aOff = (uint32_t)((((lane >> 3) & 1) * 8 + (lane & 7)) * 288 + (lane >> 4) * 16);
    // B x2: group0 {rows,k0}, group1 {rows,k0+4}  (lanes 16-31 unused but valid)
    const uint32_t bOff = (uint32_t)((lane & 7) * 288 + ((lane >> 3) & 1) * 16);

    const float xbase = (float)(l0 & (WW - 1));

    float acc[2][4][4];
    #pragma unroll
    for (int i = 0; i < 2; i++)
        #pragma unroll
        for (int j = 0; j < 4; j++)
            #pragma unroll
            for (int q = 0; q < 4; q++) acc[i][j][q] = 0.f;

    // ======== layer 1: C1 = W0' @ Xc, K=64 (8 k8-chunks), ldmatrix loads ========
    {
        const uint32_t aBase = sb + W0_O + mh * 32 * 288 + aOff;
        const uint32_t bBase = sb + X_O + ng * 32 * 288 + bOff;
        #pragma unroll
        for (int kc = 0; kc < 8; kc++) {
            uint32_t kb = kc * 32;
            uint32_t a[2][4], b[4][2];
            ldsm4(a[0], aBase + kb);
            ldsm4(a[1], aBase + 16 * 288 + kb);
            #pragma unroll
            for (int nt = 0; nt < 4; nt++)
                ldsm2(b[nt], bBase + nt * 8 * 288 + kb);
            #pragma unroll
            for (int mt = 0; mt < 2; mt++)
                #pragma unroll
                for (int nt = 0; nt < 4; nt++)
                    mmatf32(acc[mt][nt], a[mt], b[nt][0], b[nt][1]);
        }
    }
    __syncthreads();   // all reads of X done before H overwrites it

    // ---- epilogue 1: relu(C1 + b0' + w0x*xcoord) -> H [px][k] tf32 ----
    {
        uint32_t* H = sw + H_O / 4;
        #pragma unroll
        for (int mt = 0; mt < 2; mt++)
            #pragma unroll
            for (int nt = 0; nt < 4; nt++) {
                int r0  = mh * 32 + mt * 16 + g;
                int px0 = ng * 32 + nt * 8 + t * 2;
                float xc0 = xbase + (float)px0;
                float xc1 = xc0 + 1.f;
                float ba = sb0f[r0],     wa = sWx[r0];
                float bb = sb0f[r0 + 8], wb = sWx[r0 + 8];
                float v00 = acc[mt][nt][0] + ba + wa * xc0; v00 = v00 > 0.f ? v00 : 0.f;
                float v01 = acc[mt][nt][1] + ba + wa * xc1; v01 = v01 > 0.f ? v01 : 0.f;
                float v10 = acc[mt][nt][2] + bb + wb * xc0; v10 = v10 > 0.f ? v10 : 0.f;
                float v11 = acc[mt][nt][3] + bb + wb * xc1; v11 = v11 > 0.f ? v11 : 0.f;
                H[px0 * KS + r0]           = f2tf(v00);
                H[(px0 + 1) * KS + r0]     = f2tf(v01);
                H[px0 * KS + r0 + 8]       = f2tf(v10);
                H[(px0 + 1) * KS + r0 + 8] = f2tf(v11);
            }
    }
    __syncthreads();

    // ======== layer 2: C2 = W1 @ H, K=64, ldmatrix loads ========
    #pragma unroll
    for (int i = 0; i < 2; i++)
        #pragma unroll
        for (int j = 0; j < 4; j++)
            #pragma unroll
            for (int q = 0; q < 4; q++) acc[i][j][q] = 0.f;
    {
        const uint32_t aBase = sb + W1_O + mh * 32 * 288 + aOff;
        const uint32_t bBase = sb + H_O + ng * 32 * 288 + bOff;
        #pragma unroll
        for (int kc = 0; kc < 8; kc++) {
            uint32_t kb = kc * 32;
            uint32_t a[2][4], b[4][2];
            ldsm4(a[0], aBase + kb);
            ldsm4(a[1], aBase + 16 * 288 + kb);
            #pragma unroll
            for (int nt = 0; nt < 4; nt++)
                ldsm2(b[nt], bBase + nt * 8 * 288 + kb);
            #pragma unroll
            for (int mt = 0; mt < 2; mt++)
                #pragma unroll
                for (int nt = 0; nt < 4; nt++)
                    mmatf32(acc[mt][nt], a[mt], b[nt][0], b[nt][1]);
        }
    }

    // ---- epilogue 2 + layer 3 in registers ----
    float part[8];
    #pragma unroll
    for (int i = 0; i < 8; i++) part[i] = 0.f;
    #pragma unroll
    for (int mt = 0; mt < 2; mt++)
        #pragma unroll
        for (int nt = 0; nt < 4; nt++) {
            int r0 = mh * 32 + mt * 16 + g;
            float w2a = sw2[r0], w2b = sw2[r0 + 8];
            float v00 = acc[mt][nt][0] + sb1[r0];     v00 = v00 > 0.f ? v00 : 0.f;
            float v01 = acc[mt][nt][1] + sb1[r0];     v01 = v01 > 0.f ? v01 : 0.f;
            float v10 = acc[mt][nt][2] + sb1[r0 + 8]; v10 = v10 > 0.f ? v10 : 0.f;
            float v11 = acc[mt][nt][3] + sb1[r0 + 8]; v11 = v11 > 0.f ? v11 : 0.f;
            part[nt * 2]     += w2a * v00 + w2b * v10;
            part[nt * 2 + 1] += w2a * v01 + w2b * v11;
        }
    #pragma unroll
    for (int i = 0; i < 8; i++) {
        part[i] += __shfl_xor_sync(0xffffffffu, part[i], 4);
        part[i] += __shfl_xor_sync(0xffffffffu, part[i], 8);
        part[i] += __shfl_xor_sync(0xffffffffu, part[i], 16);
    }
    if (g == 0) {
        #pragma unroll
        for (int nt = 0; nt < 4; nt++) {
            int px0 = ng * 32 + nt * 8 + t * 2;
            sPart[mh * 128 + px0]     = part[nt * 2];
            sPart[mh * 128 + px0 + 1] = part[nt * 2 + 1];
        }
    }
    __syncthreads();

    if (tid < TP) {
        out[(size_t)inst * LL + l0 + tid] = sb2[0] + sPart[tid] + sPart[128 + tid];
    }
}

extern "C" void kernel_launch(void* const* d_in, const int* in_sizes, int n_in,
                              void* d_out, int out_size)
{
    const float* x      = (const float*)d_in[0];
    const float* params = (const float*)d_in[1];
    float* out = (float*)d_out;
    (void)in_sizes; (void)n_in; (void)out_size;

    cudaFuncSetAttribute(condlane_mma_kernel,
                         cudaFuncAttributeMaxDynamicSharedMemorySize, SMEM_TOTAL);

    dim3 gp(LL / TP + 8, 4);   // 320 X-tiles + 8x4 = 32 weight blocks
    prep_kernel<<<gp, 256>>>(x, params);

    dim3 grid(LL / TP, NINST);   // 320 x 32
    condlane_mma_kernel<<<grid, NTHR, SMEM_TOTAL>>>(params, out);
}

// round 17
// speedup vs baseline: 1.4450x; 1.4450x over previous
#include <cuda_runtime.h>
#include <cstdint>

#define CC   64
#define CINN 66
#define LL   40960
#define WW   256
#define TP   128
#define NTHR 256
#define NINST 32
#define NPARAMS 8513

#define OFF_W0 0
#define OFF_W1 4224
#define OFF_W2 8320
#define OFF_B0 8384
#define OFF_B1 8448
#define OFF_B2 8512
#define MASK_BIAS_SHIFT 2.19f

#define KS 68      // smem word stride per row (272 B = 17 x 16B, ODD -> conflict-free ldmatrix)
#define RB 272     // row bytes
#define KP 64      // packed global K (no pad)

// ---- precomputed tf32 operands (device globals; allocation-free) ----
__device__ __align__(16) uint32_t gX[4 * LL * KP];
#define WIMG_U32 (2 * 64 * KP)
__device__ __align__(16) uint32_t gWt[NINST * WIMG_U32];

// ---- GEMM smem byte offsets ----
#define W0_O 0          // 64 * 272 = 17408
#define W1_O 17408
#define X_O  34816      // 128 * 272 = 34816
#define H_O  34816      // H aliases X exactly
#define MISC_O 69632
#define SMEM_TOTAL (MISC_O + 2080)   // 71712 B -> 3 blocks/SM

__device__ __forceinline__ uint32_t f2tf(float v) {
    uint32_t r;
    asm("cvt.rna.tf32.f32 %0, %1;" : "=r"(r) : "f"(v));
    return r;
}
__device__ __forceinline__ uint32_t smem_u32(const void* p) {
    uint32_t a;
    asm("{ .reg .u64 t; cvta.to.shared.u64 t, %1; cvt.u32.u64 %0, t; }" : "=r"(a) : "l"(p));
    return a;
}
__device__ __forceinline__ void cpasync16(uint32_t dst, const void* src) {
    asm volatile("cp.async.cg.shared.global [%0], [%1], 16;" :: "r"(dst), "l"(src) : "memory");
}
__device__ __forceinline__ void ldsm4(uint32_t* r, uint32_t addr) {
    asm volatile("ldmatrix.sync.aligned.m8n8.x4.shared.b16 {%0,%1,%2,%3}, [%4];"
                 : "=r"(r[0]), "=r"(r[1]), "=r"(r[2]), "=r"(r[3]) : "r"(addr));
}
__device__ __forceinline__ void ldsm2(uint32_t* r, uint32_t addr) {
    asm volatile("ldmatrix.sync.aligned.m8n8.x2.shared.b16 {%0,%1}, [%2];"
                 : "=r"(r[0]), "=r"(r[1]) : "r"(addr));
}
__device__ __forceinline__ void mmatf32(float* c, const uint32_t* a, uint32_t b0, uint32_t b1) {
    asm volatile(
        "mma.sync.aligned.m16n8k8.row.col.f32.tf32.tf32.f32 "
        "{%0,%1,%2,%3}, {%4,%5,%6,%7}, {%8,%9}, {%0,%1,%2,%3};"
        : "+f"(c[0]), "+f"(c[1]), "+f"(c[2]), "+f"(c[3])
        : "r"(a[0]), "r"(a[1]), "r"(a[2]), "r"(a[3]), "r"(b0), "r"(b1));
}

// ============ fused prep: bx<320 -> X tiles; bx>=320 -> weights ============
__global__ __launch_bounds__(256)
void prep_kernel(const float* __restrict__ x, const float* __restrict__ params)
{
    __shared__ __align__(16) float stage[TP * 89];
    const int bx  = blockIdx.x;
    const int by  = blockIdx.y;
    const int tid = threadIdx.x;

    if (bx >= LL / TP) {
        const int inst = (bx - LL / TP) * 4 + by;
        const float* p = params + (size_t)inst * NPARAMS;
        uint32_t* w = gWt + (size_t)inst * WIMG_U32;
        for (int idx = tid; idx < 64 * KP; idx += 256) {
            int m = idx >> 6, k = idx & 63;
            w[idx]           = f2tf(p[OFF_W0 + m * CINN + k + 2]);  // coord cols dropped
            w[64 * KP + idx] = f2tf(p[OFF_W1 + m * 64 + k]);
        }
        return;
    }

    const int img = by;
    const int l0  = bx * TP;
    const float* xb = x + (size_t)img * CC * LL + l0;
    for (int idx = tid; idx < CC * TP; idx += 256) {
        int ch = idx >> 7, px = idx & 127;
        stage[px * 89 + ch] = xb[(size_t)ch * LL + px];
    }
    __syncthreads();

    uint4* go = (uint4*)(gX + ((size_t)img * LL + l0) * KP);
    for (int idx = tid; idx < TP * (KP / 4); idx += 256) {
        int px = idx >> 4, c4 = (idx & 15) * 4;
        const float* s = stage + px * 89 + c4;
        uint4 v;
        v.x = f2tf(s[0]); v.y = f2tf(s[1]); v.z = f2tf(s[2]); v.w = f2tf(s[3]);
        go[idx] = v;
    }
}

// ============ main GEMM kernel ============
extern __shared__ __align__(16) char smem[];

__global__ __launch_bounds__(NTHR, 3)
void condlane_mma_kernel(const float* __restrict__ params,
                         float* __restrict__ out)
{
    uint32_t* sw   = (uint32_t*)smem;
    float*    sb0f = (float*)(smem + MISC_O);   // b0 + w0[:,1]*y
    float*    sb1  = sb0f + 64;
    float*    sw2  = sb0f + 128;
    float*    sWx  = sb0f + 192;                // w0[:,0]
    float*    sb2  = sb0f + 256;
    float*    sPart = sb0f + 260;               // [2][128]

    const int bx   = blockIdx.x;
    const int inst = blockIdx.y;
    const int img  = inst >> 3;
    const int tid  = threadIdx.x;
    const int wid  = tid >> 5;
    const int lane = tid & 31;
    const int l0   = bx * TP;
    const uint32_t sb = smem_u32(smem);

    // ---- cp.async copy-in, packed-K global -> 272B-strided smem rows ----
    {
        const uint4* wsrc = (const uint4*)(gWt + (size_t)inst * WIMG_U32);
        const uint4* xsrc = (const uint4*)(gX + ((size_t)img * LL + l0) * KP);
        for (int i = tid; i < 2048; i += NTHR) {
            int row = i >> 4, c = i & 15;
            cpasync16(sb + row * RB + c * 16, wsrc + i);        // W0 rows 0-63, W1 rows 64-127
            cpasync16(sb + X_O + row * RB + c * 16, xsrc + i);  // X rows 0-127
        }
        const float* p = params + (size_t)inst * NPARAMS;
        const float yc = (float)(l0 >> 8);
        if (tid < 64) {
            sb0f[tid] = p[OFF_B0 + tid] + p[OFF_W0 + tid * CINN + 1] * yc;
            sWx[tid]  = p[OFF_W0 + tid * CINN];
            sb1[tid]  = p[OFF_B1 + tid];
            sw2[tid]  = p[OFF_W2 + tid];
        }
        if (tid == 0) sb2[0] = p[OFF_B2] - MASK_BIAS_SHIFT;
        asm volatile("cp.async.commit_group;\ncp.async.wait_group 0;" ::: "memory");
    }
    __syncthreads();

    // ---- warp tiling: 8 warps = (2 m-halves) x (4 px-groups); 32 rows x 32 px ----
    const int mh = wid & 1;
    const int ng = wid >> 1;
    const int g  = lane >> 2;
    const int t  = lane & 3;

    // ldmatrix per-lane addresses
    const uint32_t aOff = (uint32_t)((((lane >> 3) & 1) * 8 + (lane & 7)) * RB + (lane >> 4) * 16);
    const uint32_t bOff = (uint32_t)((lane & 7) * RB + ((lane >> 3) & 1) * 16);

    const float xbase = (float)(l0 & (WW - 1));

    float acc[2][4][4];
    #pragma unroll
    for (int i = 0; i < 2; i++)
        #pragma unroll
        for (int j = 0; j < 4; j++)
            #pragma unroll
            for (int q = 0; q < 4; q++) acc[i][j][q] = 0.f;

    // ======== layer 1: C1 = W0' @ Xc, K=64 (8 k8-chunks), ldmatrix loads ========
    {
        const uint32_t aBase = sb + W0_O + mh * 32 * RB + aOff;
        const uint32_t bBase = sb + X_O + ng * 32 * RB + bOff;
        #pragma unroll
        for (int kc = 0; kc < 8; kc++) {
            uint32_t kb = kc * 32;
            uint32_t a[2][4], b[4][2];
            ldsm4(a[0], aBase + kb);
            ldsm4(a[1], aBase + 16 * RB + kb);
            #pragma unroll
            for (int nt = 0; nt < 4; nt++)
                ldsm2(b[nt], bBase + nt * 8 * RB + kb);
            #pragma unroll
            for (int mt = 0; mt < 2; mt++)
                #pragma unroll
                for (int nt = 0; nt < 4; nt++)
                    mmatf32(acc[mt][nt], a[mt], b[nt][0], b[nt][1]);
        }
    }
    __syncthreads();   // all reads of X done before H overwrites it

    // ---- epilogue 1: relu(C1 + b0' + w0x*xcoord) -> H [px][k] tf32 ----
    {
        uint32_t* H = sw + H_O / 4;
        #pragma unroll
        for (int mt = 0; mt < 2; mt++)
            #pragma unroll
            for (int nt = 0; nt < 4; nt++) {
                int r0  = mh * 32 + mt * 16 + g;
                int px0 = ng * 32 + nt * 8 + t * 2;
                float xc0 = xbase + (float)px0;
                float xc1 = xc0 + 1.f;
                float ba = sb0f[r0],     wa = sWx[r0];
                float bb = sb0f[r0 + 8], wb = sWx[r0 + 8];
                float v00 = acc[mt][nt][0] + ba + wa * xc0; v00 = v00 > 0.f ? v00 : 0.f;
                float v01 = acc[mt][nt][1] + ba + wa * xc1; v01 = v01 > 0.f ? v01 : 0.f;
                float v10 = acc[mt][nt][2] + bb + wb * xc0; v10 = v10 > 0.f ? v10 : 0.f;
                float v11 = acc[mt][nt][3] + bb + wb * xc1; v11 = v11 > 0.f ? v11 : 0.f;
                H[px0 * KS + r0]           = f2tf(v00);
                H[(px0 + 1) * KS + r0]     = f2tf(v01);
                H[px0 * KS + r0 + 8]       = f2tf(v10);
                H[(px0 + 1) * KS + r0 + 8] = f2tf(v11);
            }
    }
    __syncthreads();

    // ======== layer 2: C2 = W1 @ H, K=64, ldmatrix loads ========
    #pragma unroll
    for (int i = 0; i < 2; i++)
        #pragma unroll
        for (int j = 0; j < 4; j++)
            #pragma unroll
            for (int q = 0; q < 4; q++) acc[i][j][q] = 0.f;
    {
        const uint32_t aBase = sb + W1_O + mh * 32 * RB + aOff;
        const uint32_t bBase = sb + H_O + ng * 32 * RB + bOff;
        #pragma unroll
        for (int kc = 0; kc < 8; kc++) {
            uint32_t kb = kc * 32;
            uint32_t a[2][4], b[4][2];
            ldsm4(a[0], aBase + kb);
            ldsm4(a[1], aBase + 16 * RB + kb);
            #pragma unroll
            for (int nt = 0; nt < 4; nt++)
                ldsm2(b[nt], bBase + nt * 8 * RB + kb);
            #pragma unroll
            for (int mt = 0; mt < 2; mt++)
                #pragma unroll
                for (int nt = 0; nt < 4; nt++)
                    mmatf32(acc[mt][nt], a[mt], b[nt][0], b[nt][1]);
        }
    }

    // ---- epilogue 2 + layer 3 in registers ----
    float part[8];
    #pragma unroll
    for (int i = 0; i < 8; i++) part[i] = 0.f;
    #pragma unroll
    for (int mt = 0; mt < 2; mt++)
        #pragma unroll
        for (int nt = 0; nt < 4; nt++) {
            int r0 = mh * 32 + mt * 16 + g;
            float w2a = sw2[r0], w2b = sw2[r0 + 8];
            float v00 = acc[mt][nt][0] + sb1[r0];     v00 = v00 > 0.f ? v00 : 0.f;
            float v01 = acc[mt][nt][1] + sb1[r0];     v01 = v01 > 0.f ? v01 : 0.f;
            float v10 = acc[mt][nt][2] + sb1[r0 + 8]; v10 = v10 > 0.f ? v10 : 0.f;
            float v11 = acc[mt][nt][3] + sb1[r0 + 8]; v11 = v11 > 0.f ? v11 : 0.f;
            part[nt * 2]     += w2a * v00 + w2b * v10;
            part[nt * 2 + 1] += w2a * v01 + w2b * v11;
        }
    #pragma unroll
    for (int i = 0; i < 8; i++) {
        part[i] += __shfl_xor_sync(0xffffffffu, part[i], 4);
        part[i] += __shfl_xor_sync(0xffffffffu, part[i], 8);
        part[i] += __shfl_xor_sync(0xffffffffu, part[i], 16);
    }
    if (g == 0) {
        #pragma unroll
        for (int nt = 0; nt < 4; nt++) {
            int px0 = ng * 32 + nt * 8 + t * 2;
            sPart[mh * 128 + px0]     = part[nt * 2];
            sPart[mh * 128 + px0 + 1] = part[nt * 2 + 1];
        }
    }
    __syncthreads();

    if (tid < TP) {
        out[(size_t)inst * LL + l0 + tid] = sb2[0] + sPart[tid] + sPart[128 + tid];
    }
}

extern "C" void kernel_launch(void* const* d_in, const int* in_sizes, int n_in,
                              void* d_out, int out_size)
{
    const float* x      = (const float*)d_in[0];
    const float* params = (const float*)d_in[1];
    float* out = (float*)d_out;
    (void)in_sizes; (void)n_in; (void)out_size;

    cudaFuncSetAttribute(condlane_mma_kernel,
                         cudaFuncAttributeMaxDynamicSharedMemorySize, SMEM_TOTAL);

    dim3 gp(LL / TP + 8, 4);   // 320 X-tiles + 32 weight blocks
    prep_kernel<<<gp, 256>>>(x, params);

    dim3 grid(LL / TP, NINST);   // 320 x 32
    condlane_mma_kernel<<<grid, NTHR, SMEM_TOTAL>>>(params, out);
}